// round 14
// baseline (speedup 1.0000x reference)
#include <cuda_runtime.h>
#include <cuda_bf16.h>
#include <cstdint>

#define BN 8
#define SN 2048
#define NTOK (BN*SN)
#define KSPLIT 8
#define SUBC 2                /* 128-key chunks per CTA */
#define NTHR 256              /* 8 warps; warp = 16 queries x 128 keys */
#define QPC 128               /* queries per CTA */
#define NQT (SN/QPC)          /* 16 query tiles */
#define LOG2E 1.4426950408889634f

/* Scratch (allocation-free rule: device globals), all in MMA-fragment order:
 * g_Qf: [wt = tok/16][lane][8]  a-reg order (tf32, *log2e)
 * g_Kf: [chunk = tok/128][tile = 16][lane][4]  b-frag words (tf32)
 * g_Vf: [chunk][s = 8][lane][2]  bf16x2 b-frag words for PV
 */
__device__ float    g_Qf[(size_t)NTOK * 16];
__device__ float    g_Kf[(size_t)NTOK * 16];
__device__ uint32_t g_Vf[(size_t)NTOK * 4];
__device__ float    g_den[(size_t)NTOK * KSPLIT];
__device__ float    g_num[(size_t)NTOK * KSPLIT * 8];
__device__ unsigned int g_cnt[BN * NQT];   /* zero-init; each run returns it to 0 */

__device__ __forceinline__ float ex2f(float x) {
    float y; asm("ex2.approx.ftz.f32 %0, %1;" : "=f"(y) : "f"(x)); return y;
}
__device__ __forceinline__ float tf32r(float x) {
    uint32_t u; asm("cvt.rna.tf32.f32 %0, %1;" : "=r"(u) : "f"(x));
    return __uint_as_float(u);
}
/* pack (lo,hi) -> bf16x2 word, lo in low half */
__device__ __forceinline__ uint32_t bf2(float lo, float hi) {
    uint32_t r; asm("cvt.rn.bf16x2.f32 %0, %1, %2;" : "=r"(r) : "f"(hi), "f"(lo)); return r;
}

/* tf32 m16n8k8: D += A*B  (fragment layouts verified in rounds 5/10) */
__device__ __forceinline__ void mma_tf32(float c[4], uint32_t a0, uint32_t a1,
                                         uint32_t a2, uint32_t a3,
                                         uint32_t b0, uint32_t b1) {
    asm("mma.sync.aligned.m16n8k8.row.col.f32.tf32.tf32.f32 "
        "{%0,%1,%2,%3}, {%4,%5,%6,%7}, {%8,%9}, {%0,%1,%2,%3};"
        : "+f"(c[0]), "+f"(c[1]), "+f"(c[2]), "+f"(c[3])
        : "r"(a0), "r"(a1), "r"(a2), "r"(a3), "r"(b0), "r"(b1));
}
/* bf16 m16n8k16: D += A*B */
__device__ __forceinline__ void mma_bf16(float c[4], uint32_t a0, uint32_t a1,
                                         uint32_t a2, uint32_t a3,
                                         uint32_t b0, uint32_t b1) {
    asm("mma.sync.aligned.m16n8k16.row.col.f32.bf16.bf16.f32 "
        "{%0,%1,%2,%3}, {%4,%5,%6,%7}, {%8,%9}, {%0,%1,%2,%3};"
        : "+f"(c[0]), "+f"(c[1]), "+f"(c[2]), "+f"(c[3])
        : "r"(a0), "r"(a1), "r"(a2), "r"(a3), "r"(b0), "r"(b1));
}

/* ---------------- Kernel 1: features -> fragment-ordered buffers ---------------- */
__device__ __forceinline__ void load_x8(const float* __restrict__ x, int tok, float xv[8]) {
    const float4* xp = reinterpret_cast<const float4*>(x + (size_t)tok * 8);
    float4 xa = xp[0], xb = xp[1];
    xv[0]=xa.x; xv[1]=xa.y; xv[2]=xa.z; xv[3]=xa.w;
    xv[4]=xb.x; xv[5]=xb.y; xv[6]=xb.z; xv[7]=xb.w;
}

__device__ __forceinline__ void qk_features16(const float xv[8], const float* __restrict__ ph,
                                              float F[16]) {
    float c[8];
#pragma unroll
    for (int u = 0; u < 8; u++) c[u] = __cosf(xv[u] + __ldg(&ph[u]));
    float q1 = c[0]*c[1], q2 = q1*c[2], q3 = q2*c[3];
    float q0 = c[1]*c[2]*c[3]*c[4]*c[5]*c[6]*c[7];
    float s0,s1,s2,s3,a0,a1,a2,a3;
    __sincosf(0.5f*q0, &s0, &a0);
    __sincosf(0.5f*q1, &s1, &a1);
    __sincosf(0.5f*q2, &s2, &a2);
    __sincosf(0.5f*q3, &s3, &a3);
    float t01[4] = {a0*a1, s0*a1, a0*s1, s0*s1};
    float t23[4] = {a2*a3, s2*a3, a2*s3, s2*s3};
#pragma unroll
    for (int m = 0; m < 16; m++) F[m] = t01[m & 3] * t23[m >> 2];
}

__global__ __launch_bounds__(128) void features_kernel(
        const float* __restrict__ x,
        const float* __restrict__ phi_q,
        const float* __restrict__ phi_k,
        const float* __restrict__ phi_v) {
    __shared__ float st[2048];   /* 8KB staging */
    const int tid = threadIdx.x;
    const int blk = blockIdx.x;              /* 128-token chunk index */
    const int t = blk * 128 + tid;
    const int kind = blockIdx.y;

    float xv[8];
    load_x8(x, t, xv);

    if (kind == 0) {
        /* Q a-reg order: [wt][lane = (gg&7)*4+t4][word = (f>>2)*2 + (gg>>3)] */
        float F[16];
        qk_features16(xv, phi_q, F);
        const int wt_l = tid >> 4, gg = tid & 15;
        float* base = st + wt_l * 256 + ((gg & 7) * 4) * 8 + (gg >> 3);
#pragma unroll
        for (int f = 0; f < 16; f++)
            base[(f & 3) * 8 + (f >> 2) * 2] = tf32r(F[f] * LOG2E);
        __syncthreads();
        float4* dst = reinterpret_cast<float4*>(g_Qf + (size_t)blk * 2048);
        const float4* s4 = reinterpret_cast<const float4*>(st);
#pragma unroll
        for (int i = 0; i < 4; i++) dst[tid + i * 128] = s4[tid + i * 128];
    } else if (kind == 1) {
        /* K b-frag order: [tile = kk>>3][lane = (kk&7)*4+t4][word = f>>2] */
        float F[16];
        qk_features16(xv, phi_k, F);
        const int j = tid >> 3, g = tid & 7;
        float* base = st + j * 128 + g * 16;
#pragma unroll
        for (int f = 0; f < 16; f++)
            base[(f & 3) * 4 + (f >> 2)] = tf32r(F[f]);
        __syncthreads();
        float4* dst = reinterpret_cast<float4*>(g_Kf + (size_t)blk * 2048);
        const float4* s4 = reinterpret_cast<const float4*>(st);
#pragma unroll
        for (int i = 0; i < 4; i++) dst[tid + i * 128] = s4[tid + i * 128];
    } else {
        /* V bf16 pair-words in PV b-frag order */
        float c[8];
#pragma unroll
        for (int u = 0; u < 8; u++) c[u] = __cosf(xv[u] + __ldg(&phi_v[u]));
        float v[8];
        v[1] = c[0]*c[1];
#pragma unroll
        for (int w = 2; w < 8; w++) v[w] = v[w-1]*c[w];
        v[0] = c[1]*c[2]*c[3]*c[4]*c[5]*c[6]*c[7];
        const int kq = tid;
        const int p = kq >> 1, h = kq & 1;
        const int s = p >> 3, rem = p & 7;
        const int w = rem >> 2, t4 = rem & 3;
        char* cb = reinterpret_cast<char*>(st) + s * 256;
#pragma unroll
        for (int cc = 0; cc < 8; cc++) {
            int word = (cc * 4 + t4) * 2 + w;
            *reinterpret_cast<__nv_bfloat16*>(cb + word * 4 + h * 2) = __float2bfloat16(v[cc]);
        }
        __syncthreads();
        if (tid < 128) {
            uint4* dst = reinterpret_cast<uint4*>(g_Vf + (size_t)blk * 512);
            dst[tid] = reinterpret_cast<const uint4*>(st)[tid];
        }
    }
}

/* ---------------- Kernel 2: mma.sync flash attention + fused finalize ----------------
 * Warp = 16 queries x 256 keys (2 chunks of 128, accumulated in C-frags).
 * KSPLIT=8 -> 1024 CTAs for occupancy (stall-bound regime, no pipe >40%).
 * S = Q.K^T via tf32 m16n8k8 (x2 k-steps); exp'd scores as bf16 A-frags feed
 * PV via m16n8k16; den via ones-in-col-0 MMA. Last CTA per (b,qtile)
 * combines the KSPLIT splits and applies the output projection.
 */
__global__ __launch_bounds__(NTHR) void attn_mma_kernel(
        const float* __restrict__ W,
        const float* __restrict__ bias,
        float* __restrict__ out) {
    __shared__ float    sKf[2048];   /* 8KB: 16 tiles x 32 lanes x 4 words */
    __shared__ uint32_t sVf[512];    /* 2KB: 8 s x 32 lanes x 2 words */
    __shared__ unsigned int s_old;

    const int b  = blockIdx.z;
    const int ks = blockIdx.y;
    const int qt = blockIdx.x;
    const int tid = threadIdx.x;
    const int w = tid >> 5, l = tid & 31;
    const int g = l >> 2, t4 = l & 3;

    /* Q a-regs (2 k-steps x 4 regs), loaded once per CTA */
    uint32_t qa[8];
    {
        const int wt = b * 128 + qt * 8 + w;
        const float4* qp = reinterpret_cast<const float4*>(
            g_Qf + (size_t)wt * 256 + (size_t)l * 8);
        float4 q0 = qp[0], q1 = qp[1];
        qa[0]=__float_as_uint(q0.x); qa[1]=__float_as_uint(q0.y);
        qa[2]=__float_as_uint(q0.z); qa[3]=__float_as_uint(q0.w);
        qa[4]=__float_as_uint(q1.x); qa[5]=__float_as_uint(q1.y);
        qa[6]=__float_as_uint(q1.z); qa[7]=__float_as_uint(q1.w);
    }

    /* ones-in-col-0 B-frag for the den MMA */
    const uint32_t ones = (g == 0) ? 0x3F803F80u : 0u;

    float o[4]  = {0.f,0.f,0.f,0.f};
    float o2[4] = {0.f,0.f,0.f,0.f};

    for (int c4 = 0; c4 < SUBC; c4++) {
        const int chunk = b * 16 + ks * SUBC + c4;
        __syncthreads();
        {
            const float4* kg = reinterpret_cast<const float4*>(g_Kf + (size_t)chunk * 2048);
            float4* sk4 = reinterpret_cast<float4*>(sKf);
#pragma unroll
            for (int i = 0; i < 2; i++) sk4[tid + i * NTHR] = kg[tid + i * NTHR];
            if (tid < 128) {
                const uint4* vg = reinterpret_cast<const uint4*>(g_Vf + (size_t)chunk * 512);
                reinterpret_cast<uint4*>(sVf)[tid] = vg[tid];
            }
        }
        __syncthreads();

#pragma unroll
        for (int s = 0; s < 8; s++) {
            const float4 kb0 = *reinterpret_cast<const float4*>(&sKf[(2*s)     * 128 + l * 4]);
            const float4 kb1 = *reinterpret_cast<const float4*>(&sKf[(2*s + 1) * 128 + l * 4]);

            float c0[4] = {0.f,0.f,0.f,0.f}, c1[4] = {0.f,0.f,0.f,0.f};
            mma_tf32(c0, qa[0],qa[1],qa[2],qa[3], __float_as_uint(kb0.x), __float_as_uint(kb0.y));
            mma_tf32(c1, qa[0],qa[1],qa[2],qa[3], __float_as_uint(kb1.x), __float_as_uint(kb1.y));
            mma_tf32(c0, qa[4],qa[5],qa[6],qa[7], __float_as_uint(kb0.z), __float_as_uint(kb0.w));
            mma_tf32(c1, qa[4],qa[5],qa[6],qa[7], __float_as_uint(kb1.z), __float_as_uint(kb1.w));

            float e00 = ex2f(fabsf(c0[0])), e01 = ex2f(fabsf(c0[1]));
            float e02 = ex2f(fabsf(c0[2])), e03 = ex2f(fabsf(c0[3]));
            float e10 = ex2f(fabsf(c1[0])), e11 = ex2f(fabsf(c1[1]));
            float e12 = ex2f(fabsf(c1[2])), e13 = ex2f(fabsf(c1[3]));

            uint32_t pa0 = bf2(e00, e01);
            uint32_t pa1 = bf2(e02, e03);
            uint32_t pa2 = bf2(e10, e11);
            uint32_t pa3 = bf2(e12, e13);

            const uint2 vb = *reinterpret_cast<const uint2*>(&sVf[s * 64 + l * 2]);
            mma_bf16(o, pa0, pa1, pa2, pa3, vb.x, vb.y);
            mma_bf16(o2, pa0, pa1, pa2, pa3, ones, ones);   /* den in col 0 */
        }
    }

    /* write partials: o C-frag complete (comps 2t4,2t4+1 per row);
     * den = o2[0] (row g), o2[2] (row g+8) valid at t4==0 (col 0). */
    const int tokA = b * SN + qt * QPC + w * 16 + g;
    const int tokB = tokA + 8;
    reinterpret_cast<float2*>(g_num + ((size_t)tokA * KSPLIT + ks) * 8)[t4] =
        make_float2(o[0], o[1]);
    reinterpret_cast<float2*>(g_num + ((size_t)tokB * KSPLIT + ks) * 8)[t4] =
        make_float2(o[2], o[3]);
    if (t4 == 0) {
        g_den[(size_t)tokA * KSPLIT + ks] = o2[0];
        g_den[(size_t)tokB * KSPLIT + ks] = o2[2];
    }

    /* ---- fused finalize: last-arriving CTA per (b,qt) ---- */
    __threadfence();
    if (tid == 0) s_old = atomicAdd(&g_cnt[b * NQT + qt], 1u);
    __syncthreads();

    if (s_old == KSPLIT - 1) {
        if (tid < QPC) {
            const int t = b * SN + qt * QPC + tid;
            float den = 0.f, num[8];
#pragma unroll
            for (int e = 0; e < 8; e++) num[e] = 0.f;
#pragma unroll
            for (int s = 0; s < KSPLIT; s++) {
                den += g_den[(size_t)t * KSPLIT + s];
                const float4* p = reinterpret_cast<const float4*>(
                    g_num + ((size_t)t * KSPLIT + s) * 8);
                float4 p0 = p[0], p1 = p[1];
                num[0] += p0.x; num[1] += p0.y; num[2] += p0.z; num[3] += p0.w;
                num[4] += p1.x; num[5] += p1.y; num[6] += p1.z; num[7] += p1.w;
            }
            float inv = 1.0f / den;
            float oo[8];
#pragma unroll
            for (int e = 0; e < 8; e++) oo[e] = num[e] * inv;
#pragma unroll
            for (int d = 0; d < 8; d++) {
                float y = __ldg(&bias[d]);
#pragma unroll
                for (int e = 0; e < 8; e++) y += oo[e] * __ldg(&W[d * 8 + e]);
                out[(size_t)t * 8 + d] = y;
            }
        }
        if (tid == 0) g_cnt[b * NQT + qt] = 0;   /* reset for next replay */
    }
}

extern "C" void kernel_launch(void* const* d_in, const int* in_sizes, int n_in,
                              void* d_out, int out_size) {
    const float* x     = (const float*)d_in[0];
    const float* phi_q = (const float*)d_in[1];
    const float* phi_k = (const float*)d_in[2];
    const float* phi_v = (const float*)d_in[3];
    const float* W     = (const float*)d_in[4];
    const float* bias  = (const float*)d_in[5];
    float* out = (float*)d_out;

    dim3 fgrid(NTOK / 128, 3);
    features_kernel<<<fgrid, 128>>>(x, phi_q, phi_k, phi_v);

    dim3 grid(NQT, KSPLIT, BN);
    attn_mma_kernel<<<grid, NTHR>>>(W, bias, out);
}

// round 15
// speedup vs baseline: 1.0697x; 1.0697x over previous
#include <cuda_runtime.h>
#include <cuda_bf16.h>
#include <cstdint>

#define BN 8
#define SN 2048
#define NTOK (BN*SN)
#define KSPLIT 4
#define SUBC 4                /* 128-key chunks per CTA */
#define NTHR 256              /* 8 warps; warp = 16 queries x 128 keys */
#define QPC 128               /* queries per CTA */
#define NQT (SN/QPC)          /* 16 query tiles */
#define LOG2E 1.4426950408889634f

/* Scratch (allocation-free rule: device globals), all in MMA-fragment order:
 * g_Qf: [wt = tok/16][lane][8]  a-reg order (tf32, *log2e)
 * g_Kf: [chunk = tok/128][tile = 16][lane][4]  b-frag words (tf32)
 * g_Vf: [chunk][s = 8][lane][2]  bf16x2 b-frag words for PV
 */
__device__ float    g_Qf[(size_t)NTOK * 16];
__device__ float    g_Kf[(size_t)NTOK * 16];
__device__ uint32_t g_Vf[(size_t)NTOK * 4];
__device__ float    g_den[(size_t)NTOK * KSPLIT];
__device__ float    g_num[(size_t)NTOK * KSPLIT * 8];
__device__ unsigned int g_cnt[BN * NQT];   /* zero-init; each run returns it to 0 */

__device__ __forceinline__ float ex2f(float x) {
    float y; asm("ex2.approx.ftz.f32 %0, %1;" : "=f"(y) : "f"(x)); return y;
}
__device__ __forceinline__ float tf32r(float x) {
    uint32_t u; asm("cvt.rna.tf32.f32 %0, %1;" : "=r"(u) : "f"(x));
    return __uint_as_float(u);
}
/* pack (lo,hi) -> bf16x2 word, lo in low half */
__device__ __forceinline__ uint32_t bf2(float lo, float hi) {
    uint32_t r; asm("cvt.rn.bf16x2.f32 %0, %1, %2;" : "=r"(r) : "f"(hi), "f"(lo)); return r;
}

/* tf32 m16n8k8: D += A*B  (fragment layouts verified in rounds 5/10) */
__device__ __forceinline__ void mma_tf32(float c[4], uint32_t a0, uint32_t a1,
                                         uint32_t a2, uint32_t a3,
                                         uint32_t b0, uint32_t b1) {
    asm("mma.sync.aligned.m16n8k8.row.col.f32.tf32.tf32.f32 "
        "{%0,%1,%2,%3}, {%4,%5,%6,%7}, {%8,%9}, {%0,%1,%2,%3};"
        : "+f"(c[0]), "+f"(c[1]), "+f"(c[2]), "+f"(c[3])
        : "r"(a0), "r"(a1), "r"(a2), "r"(a3), "r"(b0), "r"(b1));
}
/* bf16 m16n8k16: D += A*B */
__device__ __forceinline__ void mma_bf16(float c[4], uint32_t a0, uint32_t a1,
                                         uint32_t a2, uint32_t a3,
                                         uint32_t b0, uint32_t b1) {
    asm("mma.sync.aligned.m16n8k16.row.col.f32.bf16.bf16.f32 "
        "{%0,%1,%2,%3}, {%4,%5,%6,%7}, {%8,%9}, {%0,%1,%2,%3};"
        : "+f"(c[0]), "+f"(c[1]), "+f"(c[2]), "+f"(c[3])
        : "r"(a0), "r"(a1), "r"(a2), "r"(a3), "r"(b0), "r"(b1));
}

/* ---------------- Kernel 1: features -> fragment-ordered buffers ---------------- */
__device__ __forceinline__ void load_x8(const float* __restrict__ x, int tok, float xv[8]) {
    const float4* xp = reinterpret_cast<const float4*>(x + (size_t)tok * 8);
    float4 xa = xp[0], xb = xp[1];
    xv[0]=xa.x; xv[1]=xa.y; xv[2]=xa.z; xv[3]=xa.w;
    xv[4]=xb.x; xv[5]=xb.y; xv[6]=xb.z; xv[7]=xb.w;
}

__device__ __forceinline__ void qk_features16(const float xv[8], const float* __restrict__ ph,
                                              float F[16]) {
    float c[8];
#pragma unroll
    for (int u = 0; u < 8; u++) c[u] = __cosf(xv[u] + __ldg(&ph[u]));
    float q1 = c[0]*c[1], q2 = q1*c[2], q3 = q2*c[3];
    float q0 = c[1]*c[2]*c[3]*c[4]*c[5]*c[6]*c[7];
    float s0,s1,s2,s3,a0,a1,a2,a3;
    __sincosf(0.5f*q0, &s0, &a0);
    __sincosf(0.5f*q1, &s1, &a1);
    __sincosf(0.5f*q2, &s2, &a2);
    __sincosf(0.5f*q3, &s3, &a3);
    float t01[4] = {a0*a1, s0*a1, a0*s1, s0*s1};
    float t23[4] = {a2*a3, s2*a3, a2*s3, s2*s3};
#pragma unroll
    for (int m = 0; m < 16; m++) F[m] = t01[m & 3] * t23[m >> 2];
}

__global__ __launch_bounds__(128) void features_kernel(
        const float* __restrict__ x,
        const float* __restrict__ phi_q,
        const float* __restrict__ phi_k,
        const float* __restrict__ phi_v) {
    __shared__ float st[2048];   /* 8KB staging */
    const int tid = threadIdx.x;
    const int blk = blockIdx.x;              /* 128-token chunk index */
    const int t = blk * 128 + tid;
    const int kind = blockIdx.y;

    float xv[8];
    load_x8(x, t, xv);

    if (kind == 0) {
        /* Q a-reg order: [wt][lane = (gg&7)*4+t4][word = (f>>2)*2 + (gg>>3)] */
        float F[16];
        qk_features16(xv, phi_q, F);
        const int wt_l = tid >> 4, gg = tid & 15;
        float* base = st + wt_l * 256 + ((gg & 7) * 4) * 8 + (gg >> 3);
#pragma unroll
        for (int f = 0; f < 16; f++)
            base[(f & 3) * 8 + (f >> 2) * 2] = tf32r(F[f] * LOG2E);
        __syncthreads();
        float4* dst = reinterpret_cast<float4*>(g_Qf + (size_t)blk * 2048);
        const float4* s4 = reinterpret_cast<const float4*>(st);
#pragma unroll
        for (int i = 0; i < 4; i++) dst[tid + i * 128] = s4[tid + i * 128];
    } else if (kind == 1) {
        /* K b-frag order: [tile = kk>>3][lane = (kk&7)*4+t4][word = f>>2] */
        float F[16];
        qk_features16(xv, phi_k, F);
        const int j = tid >> 3, g = tid & 7;
        float* base = st + j * 128 + g * 16;
#pragma unroll
        for (int f = 0; f < 16; f++)
            base[(f & 3) * 4 + (f >> 2)] = tf32r(F[f]);
        __syncthreads();
        float4* dst = reinterpret_cast<float4*>(g_Kf + (size_t)blk * 2048);
        const float4* s4 = reinterpret_cast<const float4*>(st);
#pragma unroll
        for (int i = 0; i < 4; i++) dst[tid + i * 128] = s4[tid + i * 128];
    } else {
        /* V bf16 pair-words in PV b-frag order */
        float c[8];
#pragma unroll
        for (int u = 0; u < 8; u++) c[u] = __cosf(xv[u] + __ldg(&phi_v[u]));
        float v[8];
        v[1] = c[0]*c[1];
#pragma unroll
        for (int w = 2; w < 8; w++) v[w] = v[w-1]*c[w];
        v[0] = c[1]*c[2]*c[3]*c[4]*c[5]*c[6]*c[7];
        const int kq = tid;
        const int p = kq >> 1, h = kq & 1;
        const int s = p >> 3, rem = p & 7;
        const int w = rem >> 2, t4 = rem & 3;
        char* cb = reinterpret_cast<char*>(st) + s * 256;
#pragma unroll
        for (int cc = 0; cc < 8; cc++) {
            int word = (cc * 4 + t4) * 2 + w;
            *reinterpret_cast<__nv_bfloat16*>(cb + word * 4 + h * 2) = __float2bfloat16(v[cc]);
        }
        __syncthreads();
        if (tid < 128) {
            uint4* dst = reinterpret_cast<uint4*>(g_Vf + (size_t)blk * 512);
            dst[tid] = reinterpret_cast<const uint4*>(st)[tid];
        }
    }
}

/* ---------------- Kernel 2: mma.sync flash attention + fused finalize ----------------
 * Warp = 16 queries x 512 keys (4 chunks of 128 accumulated in C-frags).
 * MMA-instruction-rate bound (issue% == tensor% across configs): cut MMA count
 * by computing den with scalar FADDs on the idle FMA pipe (3 MMAs/s, not 4).
 */
__global__ __launch_bounds__(NTHR) void attn_mma_kernel(
        const float* __restrict__ W,
        const float* __restrict__ bias,
        float* __restrict__ out) {
    __shared__ float    sKf[2048];   /* 8KB: 16 tiles x 32 lanes x 4 words */
    __shared__ uint32_t sVf[512];    /* 2KB: 8 s x 32 lanes x 2 words */
    __shared__ unsigned int s_old;

    const int b  = blockIdx.z;
    const int ks = blockIdx.y;
    const int qt = blockIdx.x;
    const int tid = threadIdx.x;
    const int w = tid >> 5, l = tid & 31;
    const int g = l >> 2, t4 = l & 3;

    /* Q a-regs (2 k-steps x 4 regs), loaded once per CTA */
    uint32_t qa[8];
    {
        const int wt = b * 128 + qt * 8 + w;
        const float4* qp = reinterpret_cast<const float4*>(
            g_Qf + (size_t)wt * 256 + (size_t)l * 8);
        float4 q0 = qp[0], q1 = qp[1];
        qa[0]=__float_as_uint(q0.x); qa[1]=__float_as_uint(q0.y);
        qa[2]=__float_as_uint(q0.z); qa[3]=__float_as_uint(q0.w);
        qa[4]=__float_as_uint(q1.x); qa[5]=__float_as_uint(q1.y);
        qa[6]=__float_as_uint(q1.z); qa[7]=__float_as_uint(q1.w);
    }

    float o[4] = {0.f,0.f,0.f,0.f};
    float den0 = 0.f, den1 = 0.f;   /* rows g, g+8: this thread's 4-key slices */

    for (int c4 = 0; c4 < SUBC; c4++) {
        const int chunk = b * 16 + ks * SUBC + c4;
        __syncthreads();
        {
            const float4* kg = reinterpret_cast<const float4*>(g_Kf + (size_t)chunk * 2048);
            float4* sk4 = reinterpret_cast<float4*>(sKf);
#pragma unroll
            for (int i = 0; i < 2; i++) sk4[tid + i * NTHR] = kg[tid + i * NTHR];
            if (tid < 128) {
                const uint4* vg = reinterpret_cast<const uint4*>(g_Vf + (size_t)chunk * 512);
                reinterpret_cast<uint4*>(sVf)[tid] = vg[tid];
            }
        }
        __syncthreads();

#pragma unroll
        for (int s = 0; s < 8; s++) {
            const float4 kb0 = *reinterpret_cast<const float4*>(&sKf[(2*s)     * 128 + l * 4]);
            const float4 kb1 = *reinterpret_cast<const float4*>(&sKf[(2*s + 1) * 128 + l * 4]);

            float c0[4] = {0.f,0.f,0.f,0.f}, c1[4] = {0.f,0.f,0.f,0.f};
            mma_tf32(c0, qa[0],qa[1],qa[2],qa[3], __float_as_uint(kb0.x), __float_as_uint(kb0.y));
            mma_tf32(c1, qa[0],qa[1],qa[2],qa[3], __float_as_uint(kb1.x), __float_as_uint(kb1.y));
            mma_tf32(c0, qa[4],qa[5],qa[6],qa[7], __float_as_uint(kb0.z), __float_as_uint(kb0.w));
            mma_tf32(c1, qa[4],qa[5],qa[6],qa[7], __float_as_uint(kb1.z), __float_as_uint(kb1.w));

            /* exp (scores pre-scaled by log2e) */
            float e00 = ex2f(fabsf(c0[0])), e01 = ex2f(fabsf(c0[1]));
            float e02 = ex2f(fabsf(c0[2])), e03 = ex2f(fabsf(c0[3]));
            float e10 = ex2f(fabsf(c1[0])), e11 = ex2f(fabsf(c1[1]));
            float e12 = ex2f(fabsf(c1[2])), e13 = ex2f(fabsf(c1[3]));

            /* den on the idle FMA pipe (frees one MMA slot per s) */
            den0 += (e00 + e01) + (e10 + e11);
            den1 += (e02 + e03) + (e12 + e13);

            /* S C-frag -> PV A-frag (bf16), keys 16s..16s+15 */
            uint32_t pa0 = bf2(e00, e01);
            uint32_t pa1 = bf2(e02, e03);
            uint32_t pa2 = bf2(e10, e11);
            uint32_t pa3 = bf2(e12, e13);

            const uint2 vb = *reinterpret_cast<const uint2*>(&sVf[s * 64 + l * 2]);
            mma_bf16(o, pa0, pa1, pa2, pa3, vb.x, vb.y);
        }
    }

    /* den: reduce across the 4 t4 lanes sharing each query row */
    den0 += __shfl_xor_sync(0xffffffffu, den0, 1);
    den0 += __shfl_xor_sync(0xffffffffu, den0, 2);
    den1 += __shfl_xor_sync(0xffffffffu, den1, 1);
    den1 += __shfl_xor_sync(0xffffffffu, den1, 2);

    /* write partials: o C-frag complete (comps 2t4,2t4+1 per row) */
    const int tokA = b * SN + qt * QPC + w * 16 + g;
    const int tokB = tokA + 8;
    reinterpret_cast<float2*>(g_num + ((size_t)tokA * KSPLIT + ks) * 8)[t4] =
        make_float2(o[0], o[1]);
    reinterpret_cast<float2*>(g_num + ((size_t)tokB * KSPLIT + ks) * 8)[t4] =
        make_float2(o[2], o[3]);
    if (t4 == 0) {
        g_den[(size_t)tokA * KSPLIT + ks] = den0;
        g_den[(size_t)tokB * KSPLIT + ks] = den1;
    }

    /* ---- fused finalize: last-arriving CTA per (b,qt) ---- */
    __threadfence();
    if (tid == 0) s_old = atomicAdd(&g_cnt[b * NQT + qt], 1u);
    __syncthreads();

    if (s_old == KSPLIT - 1) {
        if (tid < QPC) {
            const int t = b * SN + qt * QPC + tid;
            float den = 0.f, num[8];
#pragma unroll
            for (int e = 0; e < 8; e++) num[e] = 0.f;
#pragma unroll
            for (int s = 0; s < KSPLIT; s++) {
                den += g_den[(size_t)t * KSPLIT + s];
                const float4* p = reinterpret_cast<const float4*>(
                    g_num + ((size_t)t * KSPLIT + s) * 8);
                float4 p0 = p[0], p1 = p[1];
                num[0] += p0.x; num[1] += p0.y; num[2] += p0.z; num[3] += p0.w;
                num[4] += p1.x; num[5] += p1.y; num[6] += p1.z; num[7] += p1.w;
            }
            float inv = 1.0f / den;
            float oo[8];
#pragma unroll
            for (int e = 0; e < 8; e++) oo[e] = num[e] * inv;
#pragma unroll
            for (int d = 0; d < 8; d++) {
                float y = __ldg(&bias[d]);
#pragma unroll
                for (int e = 0; e < 8; e++) y += oo[e] * __ldg(&W[d * 8 + e]);
                out[(size_t)t * 8 + d] = y;
            }
        }
        if (tid == 0) g_cnt[b * NQT + qt] = 0;   /* reset for next replay */
    }
}

extern "C" void kernel_launch(void* const* d_in, const int* in_sizes, int n_in,
                              void* d_out, int out_size) {
    const float* x     = (const float*)d_in[0];
    const float* phi_q = (const float*)d_in[1];
    const float* phi_k = (const float*)d_in[2];
    const float* phi_v = (const float*)d_in[3];
    const float* W     = (const float*)d_in[4];
    const float* bias  = (const float*)d_in[5];
    float* out = (float*)d_out;

    dim3 fgrid(NTOK / 128, 3);
    features_kernel<<<fgrid, 128>>>(x, phi_q, phi_k, phi_v);

    dim3 grid(NQT, KSPLIT, BN);
    attn_mma_kernel<<<grid, NTHR>>>(W, bias, out);
}